// round 16
// baseline (speedup 1.0000x reference)
#include <cuda_runtime.h>
#include <cuda_fp16.h>
#include <math.h>
#include <stdint.h>

// ---------------- problem constants ----------------
#define MAXN 100000
#define MAXE 1000000
#define GG 250
#define NEGSLOPE 0.2f
#define SCAN_BLK 1024
#define SCAN_NB ((MAXN + SCAN_BLK - 1) / SCAN_BLK)

// ---------------- static device scratch ----------------
__device__ __half g_yin[MAXN * 128];   // transformed features, in-direction
__device__ __half g_yout[MAXN * 128];  // transformed features, out-direction
__device__ __half g_h0[MAXN * 128];    // layer0 output
__device__ __half g_h1[MAXN * 128];    // layer1 output
__device__ __half g_glh[MAXN * 128];   // GAT left transform
__device__ __half g_grh[MAXN * 128];   // GAT right transform
__device__ float g_out2[MAXN * 128];   // GAT aggregate (fp32)
__device__ int   g_degi[MAXN], g_dego[MAXN];
__device__ int   g_rowI[MAXN], g_rowO[MAXN];
__device__ int   g_curI[MAXN], g_curO[MAXN];
__device__ int   g_partI[SCAN_NB + 32], g_partO[SCAN_NB + 32];
__device__ float g_dinvd[MAXN], g_dinvs[MAXN];
__device__ int   g_snode[MAXE];
__device__ float g_coefI[MAXE];
__device__ float g_eaI[MAXE];
__device__ int   g_dnode[MAXE];
__device__ float g_coefO[MAXE];
__device__ float g_cnt[GG];
__device__ float g_pool1[GG * 128], g_pool2[GG * 128];
__device__ float g_z[GG * 256];

// ---------------- helpers ----------------
__device__ __forceinline__ void red4(float* p, float a, float b, float c, float d) {
    asm volatile("red.global.add.v4.f32 [%0], {%1,%2,%3,%4};"
                 :: "l"(p), "f"(a), "f"(b), "f"(c), "f"(d) : "memory");
}
__device__ __forceinline__ float lrelu(float x) {
    return (x > 0.f) ? x : NEGSLOPE * x;
}
__device__ __forceinline__ uint32_t f2tf(float f) {
    uint32_t u;
    asm("cvt.rna.tf32.f32 %0, %1;" : "=r"(u) : "f"(f));
    return u;
}
__device__ __forceinline__ void mma_tf32(float c[4], const uint32_t a[4], uint32_t b0, uint32_t b1) {
    asm volatile(
        "mma.sync.aligned.m16n8k8.row.col.f32.tf32.tf32.f32 "
        "{%0,%1,%2,%3}, {%4,%5,%6,%7}, {%8,%9}, {%0,%1,%2,%3};"
        : "+f"(c[0]), "+f"(c[1]), "+f"(c[2]), "+f"(c[3])
        : "r"(a[0]), "r"(a[1]), "r"(a[2]), "r"(a[3]), "r"(b0), "r"(b1));
}
// load 4 consecutive fp16 cols (uint2) and widen to fp32
__device__ __forceinline__ float4 ld_h4(const uint2* __restrict__ base, long long idx) {
    uint2 u = __ldg(&base[idx]);
    __half2 p0 = *(__half2*)&u.x;
    __half2 p1 = *(__half2*)&u.y;
    float2 f0 = __half22float2(p0);
    float2 f1 = __half22float2(p1);
    return make_float4(f0.x, f0.y, f1.x, f1.y);
}

// ---------------- setup kernels ----------------
__global__ void zero_misc(int* degi, int* dego, float* cnt,
                          float* pool1, float* pool2, int nN) {
    int i = blockIdx.x * blockDim.x + threadIdx.x;
    if (i < nN) { degi[i] = 0; dego[i] = 0; }
    if (i < GG) cnt[i] = 0.f;
    if (i < GG * 128) { pool1[i] = 0.f; pool2[i] = 0.f; }
}

__global__ void deg_kernel(const int* __restrict__ src, const int* __restrict__ dst,
                           int* degi, int* dego, int nE) {
    int e = blockIdx.x * blockDim.x + threadIdx.x;
    if (e >= nE) return;
    atomicAdd(&degi[dst[e]], 1);
    atomicAdd(&dego[src[e]], 1);
}

__global__ void dinv_kernel(const int* __restrict__ degi, const int* __restrict__ dego,
                            float* dd, float* ds,
                            const int* __restrict__ batch, float* cnt, int n) {
    int i = blockIdx.x * blockDim.x + threadIdx.x;
    if (i >= n) return;
    int a = degi[i], b = dego[i];
    dd[i] = (a > 0) ? rsqrtf((float)a) : 0.f;
    ds[i] = (b > 0) ? rsqrtf((float)b) : 0.f;
    atomicAdd(&cnt[batch[i]], 1.f);
}

// exclusive scan, phase A
__global__ __launch_bounds__(SCAN_BLK) void scanA(
    const int* __restrict__ degi, const int* __restrict__ dego,
    int* rowI, int* rowO, int* partI, int* partO, int n)
{
    const int* in = blockIdx.y ? dego : degi;
    int* out = blockIdx.y ? rowO : rowI;
    int* part = blockIdx.y ? partO : partI;
    int i = blockIdx.x * SCAN_BLK + threadIdx.x;
    int v = (i < n) ? in[i] : 0;
    int lane = threadIdx.x & 31, wid = threadIdx.x >> 5;
    int p = v;
#pragma unroll
    for (int o = 1; o < 32; o <<= 1) { int t = __shfl_up_sync(~0u, p, o); if (lane >= o) p += t; }
    __shared__ int ws[32];
    if (lane == 31) ws[wid] = p;
    __syncthreads();
    if (wid == 0) {
        int s = ws[lane];
#pragma unroll
        for (int o = 1; o < 32; o <<= 1) { int t = __shfl_up_sync(~0u, s, o); if (lane >= o) s += t; }
        ws[lane] = s;
    }
    __syncthreads();
    int base = wid ? ws[wid - 1] : 0;
    if (i < n) out[i] = base + p - v;
    if (threadIdx.x == SCAN_BLK - 1) part[blockIdx.x] = base + p;
}

__global__ __launch_bounds__(128) void scanB(int* partI, int* partO, int nb) {
    int* part = blockIdx.x ? partO : partI;
    int tid = threadIdx.x;
    int v = (tid < nb) ? part[tid] : 0;
    int lane = tid & 31, wid = tid >> 5;
    int p = v;
#pragma unroll
    for (int o = 1; o < 32; o <<= 1) { int t = __shfl_up_sync(~0u, p, o); if (lane >= o) p += t; }
    __shared__ int ws[4];
    if (lane == 31) ws[wid] = p;
    __syncthreads();
    int base = 0;
    for (int w = 0; w < wid; w++) base += ws[w];
    if (tid < nb) part[tid] = base + p - v;
}

__global__ __launch_bounds__(SCAN_BLK) void scanC(
    int* rowI, int* rowO, const int* __restrict__ partI, const int* __restrict__ partO,
    int* curI, int* curO, int n)
{
    int i = blockIdx.x * SCAN_BLK + threadIdx.x;
    if (i >= n) return;
    if (blockIdx.y == 0) { int r = rowI[i] + partI[blockIdx.x]; rowI[i] = r; curI[i] = r; }
    else                 { int r = rowO[i] + partO[blockIdx.x]; rowO[i] = r; curO[i] = r; }
}

__global__ __launch_bounds__(256) void build_perm(
    const int* __restrict__ src, const int* __restrict__ dst, const float* __restrict__ ea,
    const float* __restrict__ dinvd, const float* __restrict__ dinvs,
    int* curI, int* curO,
    int* snode, float* coefI, float* eaI,
    int* dnode, float* coefO, int nE)
{
    int e = blockIdx.x * blockDim.x + threadIdx.x;
    if (e >= nE) return;
    int s = src[e], d = dst[e];
    int pI = atomicAdd(&curI[d], 1);
    snode[pI] = s; coefI[pI] = dinvd[s]; eaI[pI] = ea[e];
    int pO = atomicAdd(&curO[s], 1);
    dnode[pO] = d; coefO[pO] = dinvs[d];
}

// ---------------- dual-output TF32 GEMM: out0 = A@W0, out1 = A@W1 (fp16 outputs) ----------------
#define DUAL_SMEM ((128 * 132 + 32 * 136) * 4)
template<bool HALF_A>
__global__ __launch_bounds__(256) void gemm_dual(
    const void* __restrict__ A0,
    const float* __restrict__ W0, const float* __restrict__ W1,
    __half* __restrict__ out0, __half* __restrict__ out1, int n)
{
    extern __shared__ uint32_t dsm[];
    uint32_t* As = dsm;               // [128][132]
    uint32_t* Ws = As + 128 * 132;    // [32][136]
    const int tid = threadIdx.x;
    const int lane = tid & 31;
    const int wid = tid >> 5;
    const int wm = wid & 3;
    const int wn = wid >> 2;
    const int row0 = blockIdx.x * 128;
    const int lr = lane >> 2;
    const int lc = lane & 3;

#pragma unroll
    for (int i = 0; i < 16; i++) {
        int idx = i * 256 + tid;
        int r = idx >> 5;
        int c4 = idx & 31;
        int row = row0 + r;
        float4 v = make_float4(0.f, 0.f, 0.f, 0.f);
        if (row < n) {
            if (HALF_A) v = ld_h4((const uint2*)A0, (long long)row * 32 + c4);
            else        v = ((const float4*)A0)[(long long)row * 32 + c4];
        }
        uint32_t* dr = As + r * 132 + c4 * 4;
        dr[0] = f2tf(v.x); dr[1] = f2tf(v.y);
        dr[2] = f2tf(v.z); dr[3] = f2tf(v.w);
    }

#pragma unroll
    for (int p = 0; p < 2; p++) {
        const float4* W4 = (const float4*)(p ? W1 : W0);
        __half* outp = p ? out1 : out0;
        float acc[2][8][4];
#pragma unroll
        for (int mt = 0; mt < 2; mt++)
#pragma unroll
            for (int nt = 0; nt < 8; nt++)
#pragma unroll
                for (int j = 0; j < 4; j++) acc[mt][nt][j] = 0.f;

#pragma unroll
        for (int kc = 0; kc < 4; kc++) {
            __syncthreads();
#pragma unroll
            for (int i = 0; i < 4; i++) {
                int idx = i * 256 + tid;
                int r = idx >> 5;
                int c4 = idx & 31;
                float4 w = W4[(kc * 32 + r) * 32 + c4];
                uint32_t* dr = Ws + r * 136 + c4 * 4;
                dr[0] = f2tf(w.x); dr[1] = f2tf(w.y);
                dr[2] = f2tf(w.z); dr[3] = f2tf(w.w);
            }
            __syncthreads();
#pragma unroll
            for (int kk = 0; kk < 4; kk++) {
                int k0 = kc * 32 + kk * 8;
                int kw = kk * 8;
                uint32_t a[2][4];
#pragma unroll
                for (int mt = 0; mt < 2; mt++) {
                    int rb = wm * 32 + mt * 16;
                    a[mt][0] = As[(rb + lr) * 132 + k0 + lc];
                    a[mt][1] = As[(rb + 8 + lr) * 132 + k0 + lc];
                    a[mt][2] = As[(rb + lr) * 132 + k0 + 4 + lc];
                    a[mt][3] = As[(rb + 8 + lr) * 132 + k0 + 4 + lc];
                }
#pragma unroll
                for (int nt = 0; nt < 8; nt++) {
                    int nb = wn * 64 + nt * 8;
                    uint32_t b0 = Ws[(kw + lc) * 136 + nb + lr];
                    uint32_t b1 = Ws[(kw + 4 + lc) * 136 + nb + lr];
                    mma_tf32(acc[0][nt], a[0], b0, b1);
                    mma_tf32(acc[1][nt], a[1], b0, b1);
                }
            }
        }
#pragma unroll
        for (int nt = 0; nt < 8; nt++) {
            int cb = wn * 64 + nt * 8 + lc * 2;
#pragma unroll
            for (int mt = 0; mt < 2; mt++) {
                int r0 = row0 + wm * 32 + mt * 16 + lr;
#pragma unroll
                for (int h = 0; h < 2; h++) {
                    int row = r0 + h * 8;
                    if (row < n) {
                        float2 o = make_float2(acc[mt][nt][h * 2 + 0], acc[mt][nt][h * 2 + 1]);
                        ((__half2*)outp)[(long long)row * 64 + (cb >> 1)] = __float22half2_rn(o);
                    }
                }
            }
        }
    }
}

// ---------------- fused dual-direction CSR gather over transformed features ----------------
// h[v] = relu(0.5*(dinvd[v]*sum_I coefI*yin[s] + bIn) + 0.5*(dinvs[v]*sum_O coefO*yout[d] + bOut))
// Warp per node; 16 lanes x uint4(16B) cover a 256B fp16 row; two half-warps take
// alternating neighbors (2x MLP), merged by shfl_xor(16) at the end.
__global__ __launch_bounds__(256) void gather_combine(
    const uint4* __restrict__ yin, const uint4* __restrict__ yout,
    const int* __restrict__ rowI, const int* __restrict__ degI,
    const int* __restrict__ snode, const float* __restrict__ coefI,
    const float* __restrict__ dinvd,
    const int* __restrict__ rowO, const int* __restrict__ degO,
    const int* __restrict__ dnode, const float* __restrict__ coefO,
    const float* __restrict__ dinvs,
    const float* __restrict__ bIn, const float* __restrict__ bOut,
    uint4* __restrict__ outh, int nN)
{
    int t = blockIdx.x * blockDim.x + threadIdx.x;
    int node = t >> 5;
    int lane = t & 31;
    if (node >= nN) return;
    int hf = lane >> 4;       // 0 or 1
    int sub = lane & 15;      // 16B chunk within row

    float accI[8], accO[8];
#pragma unroll
    for (int j = 0; j < 8; j++) { accI[j] = 0.f; accO[j] = 0.f; }

    // in-direction
    {
        int beg = rowI[node], cnt = degI[node];
        for (int i = 0; i < cnt; i += 2) {
            int k = i + hf;
            if (k < cnt) {
                int e = beg + k;
                int s = __ldg(&snode[e]);
                float c = __ldg(&coefI[e]);
                uint4 v = __ldg(&yin[(long long)s * 16 + sub]);
                const __half2* hp = (const __half2*)&v;
#pragma unroll
                for (int j = 0; j < 4; j++) {
                    float2 f = __half22float2(hp[j]);
                    accI[j * 2 + 0] += c * f.x;
                    accI[j * 2 + 1] += c * f.y;
                }
            }
        }
    }
    // out-direction
    {
        int beg = rowO[node], cnt = degO[node];
        for (int i = 0; i < cnt; i += 2) {
            int k = i + hf;
            if (k < cnt) {
                int e = beg + k;
                int d = __ldg(&dnode[e]);
                float c = __ldg(&coefO[e]);
                uint4 v = __ldg(&yout[(long long)d * 16 + sub]);
                const __half2* hp = (const __half2*)&v;
#pragma unroll
                for (int j = 0; j < 4; j++) {
                    float2 f = __half22float2(hp[j]);
                    accO[j * 2 + 0] += c * f.x;
                    accO[j * 2 + 1] += c * f.y;
                }
            }
        }
    }
    // merge half-warps
#pragma unroll
    for (int j = 0; j < 8; j++) {
        accI[j] += __shfl_xor_sync(0xFFFFFFFFu, accI[j], 16);
        accO[j] += __shfl_xor_sync(0xFFFFFFFFu, accO[j], 16);
    }
    if (hf == 0) {
        float di = dinvd[node], ds = dinvs[node];
        uint4 o;
        __half2* op = (__half2*)&o;
#pragma unroll
        for (int j = 0; j < 4; j++) {
            int col = sub * 8 + j * 2;
            float v0 = 0.5f * (di * accI[j * 2 + 0] + __ldg(&bIn[col])) +
                       0.5f * (ds * accO[j * 2 + 0] + __ldg(&bOut[col]));
            float v1 = 0.5f * (di * accI[j * 2 + 1] + __ldg(&bIn[col + 1])) +
                       0.5f * (ds * accO[j * 2 + 1] + __ldg(&bOut[col + 1]));
            op[j] = __float22half2_rn(make_float2(fmaxf(v0, 0.f), fmaxf(v1, 0.f)));
        }
        outh[(long long)node * 16 + sub] = o;
    }
}

// ---------------- fused GATv2: single gather pass per node (fp16 gl/gr) ----------------
__global__ __launch_bounds__(256) void gat_fused(
    const uint2* __restrict__ gl2, const uint2* __restrict__ gr2,
    const int* __restrict__ rowptr, const int* __restrict__ deg,
    const int* __restrict__ snode, const float* __restrict__ eav,
    const float* __restrict__ we, const float* __restrict__ attf,
    float4* __restrict__ out2, int nN)
{
    int t = blockIdx.x * blockDim.x + threadIdx.x;
    int node = t >> 5;
    int lane = t & 31;
    if (node >= nN) return;
    float4 r = ld_h4(gr2, (long long)node * 32 + lane);
    float4 w = ((const float4*)we)[lane];
    float4 at = ((const float4*)attf)[lane];
    int beg = rowptr[node], cnt = deg[node];
    float4 acc = make_float4(0.f, 0.f, 0.f, 0.f);
    float den = 0.f;
    for (int i = 0; i <= cnt; i++) {   // i == cnt -> self loop
        int s; float a;
        if (i < cnt) { s = snode[beg + i]; a = eav[beg + i]; }
        else         { s = node; a = 1.f; }
        float4 l = ld_h4(gl2, (long long)s * 32 + lane);
        float v0 = lrelu(l.x + r.x + a * w.x);
        float v1 = lrelu(l.y + r.y + a * w.y);
        float v2 = lrelu(l.z + r.z + a * w.z);
        float v3 = lrelu(l.w + r.w + a * w.w);
        float p = v0 * at.x + v1 * at.y + v2 * at.z + v3 * at.w;
        p += __shfl_xor_sync(0xFFFFFFFFu, p, 4);
        p += __shfl_xor_sync(0xFFFFFFFFu, p, 2);
        p += __shfl_xor_sync(0xFFFFFFFFu, p, 1);
        float ex = 0.f;
        if ((lane & 7) == 0) ex = __expf(p);
        ex = __shfl_sync(0xFFFFFFFFu, ex, lane & 24);
        den += ex;
        acc.x += ex * l.x; acc.y += ex * l.y;
        acc.z += ex * l.z; acc.w += ex * l.w;
    }
    float inv = 1.f / den;
    out2[(long long)node * 32 + lane] =
        make_float4(acc.x * inv, acc.y * inv, acc.z * inv, acc.w * inv);
}

// ---------------- mean pool (h1 fp16, out2 fp32) ----------------
__global__ __launch_bounds__(256) void pool_kernel(
    const uint2* __restrict__ h2, const float4* __restrict__ o4,
    const int* __restrict__ batch,
    float* __restrict__ pool1, float* __restrict__ pool2, int n)
{
    int t = blockIdx.x * blockDim.x + threadIdx.x;
    int node = t >> 5;
    int lane = t & 31;
    if (node >= n) return;
    int g = batch[node];
    float4 hv = ld_h4(h2, (long long)node * 32 + lane);
    red4(&pool1[g * 128 + lane * 4], hv.x, hv.y, hv.z, hv.w);
    float4 ov = o4[(long long)node * 32 + lane];
    red4(&pool2[g * 128 + lane * 4], ov.x, ov.y, ov.z, ov.w);
}

// ---------------- finalize + head ----------------
__global__ void finalize_z(const float* __restrict__ pool1, const float* __restrict__ pool2,
                           const float* __restrict__ cnt, const float* __restrict__ gb,
                           float* __restrict__ z)
{
    int i = blockIdx.x * blockDim.x + threadIdx.x;
    if (i >= GG * 256) return;
    int g = i >> 8, j = i & 255;
    float c = fmaxf(cnt[g], 1.f);
    float v;
    if (j < 128) v = pool1[g * 128 + j] / c;
    else v = pool2[g * 128 + (j - 128)] / c + gb[j - 128];
    z[i] = v;
}

__global__ __launch_bounds__(128) void head_kernel(
    const float* __restrict__ z,
    const float* __restrict__ w1, const float* __restrict__ b1,
    const float* __restrict__ w2, const float* __restrict__ b2,
    float* __restrict__ out)
{
    __shared__ float zs[256];
    __shared__ float hid[128];
    int g = blockIdx.x;
    int tid = threadIdx.x;
    zs[tid] = z[g * 256 + tid];
    zs[tid + 128] = z[g * 256 + 128 + tid];
    __syncthreads();
    float acc = b1[tid];
#pragma unroll 8
    for (int k = 0; k < 256; k++) acc += zs[k] * w1[k * 128 + tid];
    hid[tid] = fmaxf(acc, 0.f);
    __syncthreads();
    if (tid < 2) {
        float s = b2[tid];
        for (int k = 0; k < 128; k++) s += hid[k] * w2[k * 2 + tid];
        out[g * 2 + tid] = s;
    }
}

// ---------------- launch ----------------
static inline int cdiv(long long a, long long b) { return (int)((a + b - 1) / b); }

extern "C" void kernel_launch(void* const* d_in, const int* in_sizes, int n_in,
                              void* d_out, int out_size)
{
    const float* x     = (const float*)d_in[0];
    const int*   ei    = (const int*)  d_in[1];
    const float* ea    = (const float*)d_in[2];
    const int*   batch = (const int*)  d_in[3];
    const float* dwin  = (const float*)d_in[4];
    const float* dbin  = (const float*)d_in[5];
    const float* dwout = (const float*)d_in[6];
    const float* dbout = (const float*)d_in[7];
    const float* gwl   = (const float*)d_in[8];
    const float* gwr   = (const float*)d_in[9];
    const float* gwe   = (const float*)d_in[10];
    const float* gatt  = (const float*)d_in[11];
    const float* gb    = (const float*)d_in[12];
    const float* w1    = (const float*)d_in[13];
    const float* b1    = (const float*)d_in[14];
    const float* w2    = (const float*)d_in[15];
    const float* b2    = (const float*)d_in[16];

    const int nN = in_sizes[0] / 128;
    const int nE = in_sizes[1] / 2;
    const int* src = ei;
    const int* dst = ei + nE;

    void *pyi, *pyo, *ph0, *ph1, *pGl, *pGr, *pO2, *pdi, *pdo, *prI, *prO, *pcI, *pcO,
         *ppI, *ppO, *pid, *pis, *psn, *pci, *pea, *pdn, *pco, *pc, *pp1, *pp2, *pz;
    cudaGetSymbolAddress(&pyi, g_yin);
    cudaGetSymbolAddress(&pyo, g_yout);
    cudaGetSymbolAddress(&ph0, g_h0);
    cudaGetSymbolAddress(&ph1, g_h1);
    cudaGetSymbolAddress(&pGl, g_glh);
    cudaGetSymbolAddress(&pGr, g_grh);
    cudaGetSymbolAddress(&pO2, g_out2);
    cudaGetSymbolAddress(&pdi, g_degi);
    cudaGetSymbolAddress(&pdo, g_dego);
    cudaGetSymbolAddress(&prI, g_rowI);
    cudaGetSymbolAddress(&prO, g_rowO);
    cudaGetSymbolAddress(&pcI, g_curI);
    cudaGetSymbolAddress(&pcO, g_curO);
    cudaGetSymbolAddress(&ppI, g_partI);
    cudaGetSymbolAddress(&ppO, g_partO);
    cudaGetSymbolAddress(&pid, g_dinvd);
    cudaGetSymbolAddress(&pis, g_dinvs);
    cudaGetSymbolAddress(&psn, g_snode);
    cudaGetSymbolAddress(&pci, g_coefI);
    cudaGetSymbolAddress(&pea, g_eaI);
    cudaGetSymbolAddress(&pdn, g_dnode);
    cudaGetSymbolAddress(&pco, g_coefO);
    cudaGetSymbolAddress(&pc, g_cnt);
    cudaGetSymbolAddress(&pp1, g_pool1);
    cudaGetSymbolAddress(&pp2, g_pool2);
    cudaGetSymbolAddress(&pz, g_z);

    __half* yin  = (__half*)pyi;
    __half* yout = (__half*)pyo;
    __half* h0   = (__half*)ph0;
    __half* h1   = (__half*)ph1;
    __half* glh  = (__half*)pGl;
    __half* grh  = (__half*)pGr;
    float* out2  = (float*)pO2;
    int*   degi  = (int*)pdi;
    int*   dego  = (int*)pdo;
    int*   rowI  = (int*)prI;
    int*   rowO  = (int*)prO;
    int*   curI  = (int*)pcI;
    int*   curO  = (int*)pcO;
    int*   partI = (int*)ppI;
    int*   partO = (int*)ppO;
    float* dinvd = (float*)pid;
    float* dinvs = (float*)pis;
    int*   snode = (int*)psn;
    float* coefI = (float*)pci;
    float* eaI   = (float*)pea;
    int*   dnode = (int*)pdn;
    float* coefO = (float*)pco;
    float* cnt   = (float*)pc;
    float* pool1 = (float*)pp1;
    float* pool2 = (float*)pp2;
    float* z     = (float*)pz;

    cudaFuncSetAttribute(gemm_dual<false>, cudaFuncAttributeMaxDynamicSharedMemorySize, DUAL_SMEM);
    cudaFuncSetAttribute(gemm_dual<true>,  cudaFuncAttributeMaxDynamicSharedMemorySize, DUAL_SMEM);

    const int T = 256;
    const int nb = cdiv(nN, SCAN_BLK);
    const int gatherBlocks = cdiv((long long)nN * 32, T);

    // 1-3: setup
    zero_misc<<<cdiv(nN, T), T>>>(degi, dego, cnt, pool1, pool2, nN);
    deg_kernel<<<cdiv(nE, T), T>>>(src, dst, degi, dego, nE);
    dinv_kernel<<<cdiv(nN, T), T>>>(degi, dego, dinvd, dinvs, batch, cnt, nN);

    // 4: GAT transforms (profiled by ncu)
    gemm_dual<false><<<cdiv(nN, 128), T, DUAL_SMEM>>>(x, gwl, gwr, glh, grh, nN);

    // 5: layer-0 transforms y = x @ W
    gemm_dual<false><<<cdiv(nN, 128), T, DUAL_SMEM>>>(x, dwin, dwout, yin, yout, nN);

    // 6-9: CSR build
    scanA<<<dim3(nb, 2), SCAN_BLK>>>(degi, dego, rowI, rowO, partI, partO, nN);
    scanB<<<2, 128>>>(partI, partO, nb);
    scanC<<<dim3(nb, 2), SCAN_BLK>>>(rowI, rowO, partI, partO, curI, curO, nN);
    build_perm<<<cdiv(nE, T), T>>>(src, dst, ea, dinvd, dinvs, curI, curO,
                                   snode, coefI, eaI, dnode, coefO, nE);

    // 10: layer-0 gather+combine -> h0 (fp16)
    gather_combine<<<gatherBlocks, T>>>(
        (const uint4*)yin, (const uint4*)yout,
        rowI, degi, snode, coefI, dinvd,
        rowO, dego, dnode, coefO, dinvs,
        dbin, dbout, (uint4*)h0, nN);

    // 11: layer-1 transforms (fp16 A)
    gemm_dual<true><<<cdiv(nN, 128), T, DUAL_SMEM>>>(h0, dwin + 128 * 128, dwout + 128 * 128,
                                                     yin, yout, nN);

    // 12: layer-1 gather+combine -> h1 (fp16)
    gather_combine<<<gatherBlocks, T>>>(
        (const uint4*)yin, (const uint4*)yout,
        rowI, degi, snode, coefI, dinvd,
        rowO, dego, dnode, coefO, dinvs,
        dbin + 128, dbout + 128, (uint4*)h1, nN);

    // 13: fused GATv2 -> out2 (fp32)
    gat_fused<<<gatherBlocks, T>>>((const uint2*)glh, (const uint2*)grh,
                                   rowI, degi, snode, eaI, gwe, gatt,
                                   (float4*)out2, nN);

    // 14: mean pool sums
    pool_kernel<<<gatherBlocks, T>>>((const uint2*)h1, (const float4*)out2,
                                     batch, pool1, pool2, nN);

    // 15-16: finalize + head
    finalize_z<<<cdiv(GG * 256, T), T>>>(pool1, pool2, cnt, gb, z);
    head_kernel<<<GG, 128>>>(z, w1, b1, w2, b2, (float*)d_out);
}